// round 13
// baseline (speedup 1.0000x reference)
#include <cuda_runtime.h>

#define BB 8
#define SS 2048
#define HH 1024
#define NT (BB * SS)   // 16384 tokens

// Scratch (device globals — no allocation allowed in kernel_launch)
// Flags PACKED into the scores: candidate==false => score = -1e30,
// so pair_score > 0 can never fire.
__device__ float g_sse[NT];     // sc ? score_s : -1e30
__device__ float g_see[NT];     // ec ? score_e (+bm) : -1e30

#define NEGBIG (-1e30f)

// ---------------------------------------------------------------------------
// Kernel 1: proven R3 structure (512 thr = 16 warps = 16 tokens/block,
// 1024 blocks; smem-folded weights; 1 streaming LDG.128 + 4 LDS.128 per
// 512B of rep). Epilogue packs candidate flags into the scores.
// ---------------------------------------------------------------------------
__global__ void __launch_bounds__(512)
logits_kernel(const float* __restrict__ rep,
              const int*   __restrict__ mask,
              const float* __restrict__ Ws,  const float* __restrict__ bs,
              const float* __restrict__ We,  const float* __restrict__ be,
              const float* __restrict__ Wm,  const float* __restrict__ bm)
{
    __shared__ float s_wds[HH];   // Ws[:,1]-Ws[:,0]
    __shared__ float s_wss[HH];   // Wm0*Ws[:,0]+Wm1*Ws[:,1]
    __shared__ float s_wde[HH];   // We[:,1]-We[:,0]
    __shared__ float s_wse[HH];   // Wm2*We[:,0]+Wm3*We[:,1]
    __shared__ float s_bias[4];

    const int tid = threadIdx.x;
    {
        const float wm0 = Wm[0], wm1 = Wm[1], wm2 = Wm[2], wm3 = Wm[3];
        #pragma unroll
        for (int p = 0; p < HH / 512; p++) {
            int h = p * 512 + tid;
            float a0 = Ws[2 * h], a1 = Ws[2 * h + 1];
            float c0 = We[2 * h], c1 = We[2 * h + 1];
            s_wds[h] = a1 - a0;
            s_wss[h] = wm0 * a0 + wm1 * a1;
            s_wde[h] = c1 - c0;
            s_wse[h] = wm2 * c0 + wm3 * c1;
        }
        if (tid == 0) {
            s_bias[0] = bs[1] - bs[0];
            s_bias[1] = wm0 * bs[0] + wm1 * bs[1];
            s_bias[2] = be[1] - be[0];
            s_bias[3] = wm2 * be[0] + wm3 * be[1] + bm[0];
        }
    }
    __syncthreads();

    const int t    = blockIdx.x * 16 + (tid >> 5);   // token id
    const int lane = tid & 31;

    const float4* r4  = reinterpret_cast<const float4*>(rep + (size_t)t * HH);
    const float4* wds = reinterpret_cast<const float4*>(s_wds);
    const float4* wss = reinterpret_cast<const float4*>(s_wss);
    const float4* wde = reinterpret_cast<const float4*>(s_wde);
    const float4* wse = reinterpret_cast<const float4*>(s_wse);

    float ds = 0.f, sv = 0.f, de = 0.f, se = 0.f;
    #pragma unroll
    for (int k = 0; k < HH / 128; k++) {
        int idx = k * 32 + lane;
        float4 r = __ldcs(&r4[idx]);         // streaming: rep is read-once
        float4 a = wds[idx];
        float4 b = wss[idx];
        float4 c = wde[idx];
        float4 d = wse[idx];
        ds += r.x*a.x + r.y*a.y + r.z*a.z + r.w*a.w;
        sv += r.x*b.x + r.y*b.y + r.z*b.z + r.w*b.w;
        de += r.x*c.x + r.y*c.y + r.z*c.z + r.w*c.w;
        se += r.x*d.x + r.y*d.y + r.z*d.z + r.w*d.w;
    }
    #pragma unroll
    for (int off = 16; off; off >>= 1) {
        ds += __shfl_xor_sync(0xffffffffu, ds, off);
        sv += __shfl_xor_sync(0xffffffffu, sv, off);
        de += __shfl_xor_sync(0xffffffffu, de, off);
        se += __shfl_xor_sync(0xffffffffu, se, off);
    }
    if (lane == 0) {
        int m  = (mask[t] != 0);
        int sc = m && ((ds + s_bias[0]) >= 0.f);   // s0 <= s1
        int ec = m && ((de + s_bias[2]) >= 0.f);   // e0 <= e1
        g_sse[t] = sc ? (sv + s_bias[1]) : NEGBIG;
        g_see[t] = ec ? (se + s_bias[3]) : NEGBIG;
    }
}

// ---------------------------------------------------------------------------
// Kernel 2: one block per (b, i) row; 512 threads x float4 covers S=2048 cols.
// A/B vs all prior rounds: PLAIN writeback stores (no .cs) — let L2 retain
// and lazily drain the 256MB write stream (126MB L2) instead of evict-first.
// ALU trimmed: masked = (j>=i) ? max(ps,0) : 0;  valid = masked>0.
// ---------------------------------------------------------------------------
__global__ void __launch_bounds__(512)
pair_kernel(float* __restrict__ out_valid,
            float* __restrict__ out_masked)
{
    const int i = blockIdx.x;
    const int b = blockIdx.y;

    const float ss = g_sse[b * SS + i];

    const size_t rowoff = ((size_t)b * SS + i) * SS;
    float4* ov = reinterpret_cast<float4*>(out_valid  + rowoff);
    float4* om = reinterpret_cast<float4*>(out_masked + rowoff);

    const int j4 = threadIdx.x;        // one float4 (4 j's) per thread
    const int j0 = j4 * 4;

    float4 v, m;
    if (ss < -1e29f || (j0 + 3) < i) {     // row dead or fully below diagonal
        v = make_float4(0.f, 0.f, 0.f, 0.f);
        m = v;
    } else {
        const float4 se4 = reinterpret_cast<const float4*>(g_see + b * SS)[j4];

        m.x = (i <= j0 + 0) ? fmaxf(ss + se4.x, 0.f) : 0.f;
        m.y = (i <= j0 + 1) ? fmaxf(ss + se4.y, 0.f) : 0.f;
        m.z = (i <= j0 + 2) ? fmaxf(ss + se4.z, 0.f) : 0.f;
        m.w = (i <= j0 + 3) ? fmaxf(ss + se4.w, 0.f) : 0.f;
        v.x = (m.x > 0.f) ? 1.f : 0.f;
        v.y = (m.y > 0.f) ? 1.f : 0.f;
        v.z = (m.z > 0.f) ? 1.f : 0.f;
        v.w = (m.w > 0.f) ? 1.f : 0.f;
    }
    ov[j4] = v;                        // plain writeback stores (A/B vs .cs)
    om[j4] = m;
}

extern "C" void kernel_launch(void* const* d_in, const int* in_sizes, int n_in,
                              void* d_out, int out_size)
{
    const float* rep  = (const float*)d_in[0];
    const int*   mask = (const int*)  d_in[1];
    const float* Ws   = (const float*)d_in[2];
    const float* bs   = (const float*)d_in[3];
    const float* We   = (const float*)d_in[4];
    const float* be   = (const float*)d_in[5];
    const float* Wm   = (const float*)d_in[6];
    const float* bm   = (const float*)d_in[7];

    float* out = (float*)d_out;
    const size_t half = (size_t)BB * SS * SS;   // valid first, masked second

    logits_kernel<<<NT / 16, 512>>>(rep, mask, Ws, bs, We, be, Wm, bm);

    dim3 g2(SS, BB);
    pair_kernel<<<g2, 512>>>(out, out + half);
}

// round 14
// speedup vs baseline: 1.0026x; 1.0026x over previous
#include <cuda_runtime.h>

#define BB 8
#define SS 2048
#define HH 1024
#define NT (BB * SS)   // 16384 tokens

// Scratch (device globals — no allocation allowed in kernel_launch)
// Flags PACKED into the scores: candidate==false => score = -1e30,
// so pair_score > 0 can never fire.
__device__ float g_sse[NT];     // sc ? score_s : -1e30
__device__ float g_see[NT];     // ec ? score_e (+bm) : -1e30

#define NEGBIG (-1e30f)

// ---------------------------------------------------------------------------
// Kernel 1: proven R3 structure (512 thr = 16 warps = 16 tokens/block,
// 1024 blocks; smem-folded weights; 1 streaming LDG.128 + 4 LDS.128 per
// 512B of rep). Epilogue packs candidate flags into the scores.
// ---------------------------------------------------------------------------
__global__ void __launch_bounds__(512)
logits_kernel(const float* __restrict__ rep,
              const int*   __restrict__ mask,
              const float* __restrict__ Ws,  const float* __restrict__ bs,
              const float* __restrict__ We,  const float* __restrict__ be,
              const float* __restrict__ Wm,  const float* __restrict__ bm)
{
    __shared__ float s_wds[HH];   // Ws[:,1]-Ws[:,0]
    __shared__ float s_wss[HH];   // Wm0*Ws[:,0]+Wm1*Ws[:,1]
    __shared__ float s_wde[HH];   // We[:,1]-We[:,0]
    __shared__ float s_wse[HH];   // Wm2*We[:,0]+Wm3*We[:,1]
    __shared__ float s_bias[4];

    const int tid = threadIdx.x;
    {
        const float wm0 = Wm[0], wm1 = Wm[1], wm2 = Wm[2], wm3 = Wm[3];
        #pragma unroll
        for (int p = 0; p < HH / 512; p++) {
            int h = p * 512 + tid;
            float a0 = Ws[2 * h], a1 = Ws[2 * h + 1];
            float c0 = We[2 * h], c1 = We[2 * h + 1];
            s_wds[h] = a1 - a0;
            s_wss[h] = wm0 * a0 + wm1 * a1;
            s_wde[h] = c1 - c0;
            s_wse[h] = wm2 * c0 + wm3 * c1;
        }
        if (tid == 0) {
            s_bias[0] = bs[1] - bs[0];
            s_bias[1] = wm0 * bs[0] + wm1 * bs[1];
            s_bias[2] = be[1] - be[0];
            s_bias[3] = wm2 * be[0] + wm3 * be[1] + bm[0];
        }
    }
    __syncthreads();

    const int t    = blockIdx.x * 16 + (tid >> 5);   // token id
    const int lane = tid & 31;

    const float4* r4  = reinterpret_cast<const float4*>(rep + (size_t)t * HH);
    const float4* wds = reinterpret_cast<const float4*>(s_wds);
    const float4* wss = reinterpret_cast<const float4*>(s_wss);
    const float4* wde = reinterpret_cast<const float4*>(s_wde);
    const float4* wse = reinterpret_cast<const float4*>(s_wse);

    float ds = 0.f, sv = 0.f, de = 0.f, se = 0.f;
    #pragma unroll
    for (int k = 0; k < HH / 128; k++) {
        int idx = k * 32 + lane;
        float4 r = __ldcs(&r4[idx]);         // streaming: rep is read-once
        float4 a = wds[idx];
        float4 b = wss[idx];
        float4 c = wde[idx];
        float4 d = wse[idx];
        ds += r.x*a.x + r.y*a.y + r.z*a.z + r.w*a.w;
        sv += r.x*b.x + r.y*b.y + r.z*b.z + r.w*b.w;
        de += r.x*c.x + r.y*c.y + r.z*c.z + r.w*c.w;
        se += r.x*d.x + r.y*d.y + r.z*d.z + r.w*d.w;
    }
    #pragma unroll
    for (int off = 16; off; off >>= 1) {
        ds += __shfl_xor_sync(0xffffffffu, ds, off);
        sv += __shfl_xor_sync(0xffffffffu, sv, off);
        de += __shfl_xor_sync(0xffffffffu, de, off);
        se += __shfl_xor_sync(0xffffffffu, se, off);
    }
    if (lane == 0) {
        int m  = (mask[t] != 0);
        int sc = m && ((ds + s_bias[0]) >= 0.f);   // s0 <= s1
        int ec = m && ((de + s_bias[2]) >= 0.f);   // e0 <= e1
        g_sse[t] = sc ? (sv + s_bias[1]) : NEGBIG;
        g_see[t] = ec ? (se + s_bias[3]) : NEGBIG;
    }
}

// ---------------------------------------------------------------------------
// Kernel 2: one block per (b, i) row; 512 threads x float4 covers S=2048 cols.
// Store-policy A/B/C: .cs=58.0, plain=61.7, now .wt (write-through) — drain
// dirty lines toward DRAM eagerly so the NEXT iteration's logits reads don't
// contend with residual L2 writeback. Warp writes 2 contiguous 128B lines.
// ---------------------------------------------------------------------------
__global__ void __launch_bounds__(512)
pair_kernel(float* __restrict__ out_valid,
            float* __restrict__ out_masked)
{
    const int i = blockIdx.x;
    const int b = blockIdx.y;

    const float ss = g_sse[b * SS + i];

    const size_t rowoff = ((size_t)b * SS + i) * SS;
    float4* ov = reinterpret_cast<float4*>(out_valid  + rowoff);
    float4* om = reinterpret_cast<float4*>(out_masked + rowoff);

    const int j4 = threadIdx.x;        // one float4 (4 j's) per thread
    const int j0 = j4 * 4;

    float4 v, m;
    if (ss < -1e29f || (j0 + 3) < i) {     // row dead or fully below diagonal
        v = make_float4(0.f, 0.f, 0.f, 0.f);
        m = v;
    } else {
        const float4 se4 = reinterpret_cast<const float4*>(g_see + b * SS)[j4];

        float ps; bool val;
        ps = ss + se4.x; val = (i <= j0 + 0) && (ps > 0.f);
        v.x = val ? 1.f : 0.f; m.x = val ? ps : 0.f;
        ps = ss + se4.y; val = (i <= j0 + 1) && (ps > 0.f);
        v.y = val ? 1.f : 0.f; m.y = val ? ps : 0.f;
        ps = ss + se4.z; val = (i <= j0 + 2) && (ps > 0.f);
        v.z = val ? 1.f : 0.f; m.z = val ? ps : 0.f;
        ps = ss + se4.w; val = (i <= j0 + 3) && (ps > 0.f);
        v.w = val ? 1.f : 0.f; m.w = val ? ps : 0.f;
    }
    __stwt(ov + j4, v);                // write-through: eager DRAM drain
    __stwt(om + j4, m);
}

extern "C" void kernel_launch(void* const* d_in, const int* in_sizes, int n_in,
                              void* d_out, int out_size)
{
    const float* rep  = (const float*)d_in[0];
    const int*   mask = (const int*)  d_in[1];
    const float* Ws   = (const float*)d_in[2];
    const float* bs   = (const float*)d_in[3];
    const float* We   = (const float*)d_in[4];
    const float* be   = (const float*)d_in[5];
    const float* Wm   = (const float*)d_in[6];
    const float* bm   = (const float*)d_in[7];

    float* out = (float*)d_out;
    const size_t half = (size_t)BB * SS * SS;   // valid first, masked second

    logits_kernel<<<NT / 16, 512>>>(rep, mask, Ws, bs, We, be, Wm, bm);

    dim3 g2(SS, BB);
    pair_kernel<<<g2, 512>>>(out, out + half);
}

// round 15
// speedup vs baseline: 1.0712x; 1.0684x over previous
#include <cuda_runtime.h>

#define BB 8
#define SS 2048
#define HH 1024
#define NT (BB * SS)   // 16384 tokens

// Scratch (device globals — no allocation allowed in kernel_launch)
// Flags PACKED into the scores: candidate==false => score = -1e30,
// so pair_score > 0 can never fire.
__device__ float g_sse[NT];     // sc ? score_s : -1e30
__device__ float g_see[NT];     // ec ? score_e (+bm) : -1e30

#define NEGBIG (-1e30f)

// ---------------------------------------------------------------------------
// Kernel 1: best-measured structure (512 thr = 16 warps = 16 tokens/block,
// 1024 blocks; smem-folded weights; 1 streaming LDG.128 + 4 LDS.128 per
// 512B of rep). Epilogue packs candidate flags into the scores.
// ---------------------------------------------------------------------------
__global__ void __launch_bounds__(512)
logits_kernel(const float* __restrict__ rep,
              const int*   __restrict__ mask,
              const float* __restrict__ Ws,  const float* __restrict__ bs,
              const float* __restrict__ We,  const float* __restrict__ be,
              const float* __restrict__ Wm,  const float* __restrict__ bm)
{
    __shared__ float s_wds[HH];   // Ws[:,1]-Ws[:,0]
    __shared__ float s_wss[HH];   // Wm0*Ws[:,0]+Wm1*Ws[:,1]
    __shared__ float s_wde[HH];   // We[:,1]-We[:,0]
    __shared__ float s_wse[HH];   // Wm2*We[:,0]+Wm3*We[:,1]
    __shared__ float s_bias[4];

    const int tid = threadIdx.x;
    {
        const float wm0 = Wm[0], wm1 = Wm[1], wm2 = Wm[2], wm3 = Wm[3];
        #pragma unroll
        for (int p = 0; p < HH / 512; p++) {
            int h = p * 512 + tid;
            float a0 = Ws[2 * h], a1 = Ws[2 * h + 1];
            float c0 = We[2 * h], c1 = We[2 * h + 1];
            s_wds[h] = a1 - a0;
            s_wss[h] = wm0 * a0 + wm1 * a1;
            s_wde[h] = c1 - c0;
            s_wse[h] = wm2 * c0 + wm3 * c1;
        }
        if (tid == 0) {
            s_bias[0] = bs[1] - bs[0];
            s_bias[1] = wm0 * bs[0] + wm1 * bs[1];
            s_bias[2] = be[1] - be[0];
            s_bias[3] = wm2 * be[0] + wm3 * be[1] + bm[0];
        }
    }
    __syncthreads();

    const int t    = blockIdx.x * 16 + (tid >> 5);   // token id
    const int lane = tid & 31;

    const float4* r4  = reinterpret_cast<const float4*>(rep + (size_t)t * HH);
    const float4* wds = reinterpret_cast<const float4*>(s_wds);
    const float4* wss = reinterpret_cast<const float4*>(s_wss);
    const float4* wde = reinterpret_cast<const float4*>(s_wde);
    const float4* wse = reinterpret_cast<const float4*>(s_wse);

    float ds = 0.f, sv = 0.f, de = 0.f, se = 0.f;
    #pragma unroll
    for (int k = 0; k < HH / 128; k++) {
        int idx = k * 32 + lane;
        float4 r = __ldcs(&r4[idx]);         // streaming: rep is read-once
        float4 a = wds[idx];
        float4 b = wss[idx];
        float4 c = wde[idx];
        float4 d = wse[idx];
        ds += r.x*a.x + r.y*a.y + r.z*a.z + r.w*a.w;
        sv += r.x*b.x + r.y*b.y + r.z*b.z + r.w*b.w;
        de += r.x*c.x + r.y*c.y + r.z*c.z + r.w*c.w;
        se += r.x*d.x + r.y*d.y + r.z*d.z + r.w*d.w;
    }
    #pragma unroll
    for (int off = 16; off; off >>= 1) {
        ds += __shfl_xor_sync(0xffffffffu, ds, off);
        sv += __shfl_xor_sync(0xffffffffu, sv, off);
        de += __shfl_xor_sync(0xffffffffu, de, off);
        se += __shfl_xor_sync(0xffffffffu, se, off);
    }
    if (lane == 0) {
        int m  = (mask[t] != 0);
        int sc = m && ((ds + s_bias[0]) >= 0.f);   // s0 <= s1
        int ec = m && ((de + s_bias[2]) >= 0.f);   // e0 <= e1
        g_sse[t] = sc ? (sv + s_bias[1]) : NEGBIG;
        g_see[t] = ec ? (se + s_bias[3]) : NEGBIG;
    }
}

// ---------------------------------------------------------------------------
// Kernel 2: TWO rows per block (grid 1024 x 8, 512 threads). The se4 row
// vector is loaded ONCE and reused for both rows (pair input LDG halved);
// per-row scalar ss from g_sse. Stores stay __stcs (measured best:
// .cs 58.0 < .wt 61.5 ~ plain 61.7). HBM-write bound: 256 MB.
// ---------------------------------------------------------------------------
__global__ void __launch_bounds__(512)
pair_kernel(float* __restrict__ out_valid,
            float* __restrict__ out_masked)
{
    const int i0 = blockIdx.x * 2;
    const int b  = blockIdx.y;
    const int j4 = threadIdx.x;        // one float4 (4 j's) per thread
    const int j0 = j4 * 4;

    const float ss0 = g_sse[b * SS + i0];
    const float ss1 = g_sse[b * SS + i0 + 1];
    const float4 se4 = reinterpret_cast<const float4*>(g_see + b * SS)[j4];

    const size_t row0 = ((size_t)b * SS + i0) * SS;
    float4* ov = reinterpret_cast<float4*>(out_valid  + row0) + j4;
    float4* om = reinterpret_cast<float4*>(out_masked + row0) + j4;

    #pragma unroll
    for (int r = 0; r < 2; r++) {
        const int   i  = i0 + r;
        const float ss = r ? ss1 : ss0;

        float4 v, m;
        if (ss < -1e29f || (j0 + 3) < i) {   // row dead or fully below diagonal
            v = make_float4(0.f, 0.f, 0.f, 0.f);
            m = v;
        } else {
            float ps; bool val;
            ps = ss + se4.x; val = (i <= j0 + 0) && (ps > 0.f);
            v.x = val ? 1.f : 0.f; m.x = val ? ps : 0.f;
            ps = ss + se4.y; val = (i <= j0 + 1) && (ps > 0.f);
            v.y = val ? 1.f : 0.f; m.y = val ? ps : 0.f;
            ps = ss + se4.z; val = (i <= j0 + 2) && (ps > 0.f);
            v.z = val ? 1.f : 0.f; m.z = val ? ps : 0.f;
            ps = ss + se4.w; val = (i <= j0 + 3) && (ps > 0.f);
            v.w = val ? 1.f : 0.f; m.w = val ? ps : 0.f;
        }
        __stcs(ov + (size_t)r * (SS / 4), v);
        __stcs(om + (size_t)r * (SS / 4), m);
    }
}

extern "C" void kernel_launch(void* const* d_in, const int* in_sizes, int n_in,
                              void* d_out, int out_size)
{
    const float* rep  = (const float*)d_in[0];
    const int*   mask = (const int*)  d_in[1];
    const float* Ws   = (const float*)d_in[2];
    const float* bs   = (const float*)d_in[3];
    const float* We   = (const float*)d_in[4];
    const float* be   = (const float*)d_in[5];
    const float* Wm   = (const float*)d_in[6];
    const float* bm   = (const float*)d_in[7];

    float* out = (float*)d_out;
    const size_t half = (size_t)BB * SS * SS;   // valid first, masked second

    logits_kernel<<<NT / 16, 512>>>(rep, mask, Ws, bs, We, be, Wm, bm);

    dim3 g2(SS / 2, BB);
    pair_kernel<<<g2, 512>>>(out, out + half);
}

// round 16
// speedup vs baseline: 1.0747x; 1.0033x over previous
#include <cuda_runtime.h>

#define BB 8
#define SS 2048
#define HH 1024
#define NT (BB * SS)   // 16384 tokens
#define RPB 4          // pair rows per block

// Scratch (device globals — no allocation allowed in kernel_launch)
// Flags PACKED into the scores: candidate==false => score = -1e30,
// so pair_score > 0 can never fire.
__device__ float g_sse[NT];     // sc ? score_s : -1e30
__device__ float g_see[NT];     // ec ? score_e (+bm) : -1e30

#define NEGBIG (-1e30f)

// ---------------------------------------------------------------------------
// Kernel 1: best-measured structure (512 thr = 16 warps = 16 tokens/block,
// 1024 blocks; smem-folded weights; 1 streaming LDG.128 + 4 LDS.128 per
// 512B of rep). Epilogue packs candidate flags into the scores.
// ---------------------------------------------------------------------------
__global__ void __launch_bounds__(512)
logits_kernel(const float* __restrict__ rep,
              const int*   __restrict__ mask,
              const float* __restrict__ Ws,  const float* __restrict__ bs,
              const float* __restrict__ We,  const float* __restrict__ be,
              const float* __restrict__ Wm,  const float* __restrict__ bm)
{
    __shared__ float s_wds[HH];   // Ws[:,1]-Ws[:,0]
    __shared__ float s_wss[HH];   // Wm0*Ws[:,0]+Wm1*Ws[:,1]
    __shared__ float s_wde[HH];   // We[:,1]-We[:,0]
    __shared__ float s_wse[HH];   // Wm2*We[:,0]+Wm3*We[:,1]
    __shared__ float s_bias[4];

    const int tid = threadIdx.x;
    {
        const float wm0 = Wm[0], wm1 = Wm[1], wm2 = Wm[2], wm3 = Wm[3];
        #pragma unroll
        for (int p = 0; p < HH / 512; p++) {
            int h = p * 512 + tid;
            float a0 = Ws[2 * h], a1 = Ws[2 * h + 1];
            float c0 = We[2 * h], c1 = We[2 * h + 1];
            s_wds[h] = a1 - a0;
            s_wss[h] = wm0 * a0 + wm1 * a1;
            s_wde[h] = c1 - c0;
            s_wse[h] = wm2 * c0 + wm3 * c1;
        }
        if (tid == 0) {
            s_bias[0] = bs[1] - bs[0];
            s_bias[1] = wm0 * bs[0] + wm1 * bs[1];
            s_bias[2] = be[1] - be[0];
            s_bias[3] = wm2 * be[0] + wm3 * be[1] + bm[0];
        }
    }
    __syncthreads();

    const int t    = blockIdx.x * 16 + (tid >> 5);   // token id
    const int lane = tid & 31;

    const float4* r4  = reinterpret_cast<const float4*>(rep + (size_t)t * HH);
    const float4* wds = reinterpret_cast<const float4*>(s_wds);
    const float4* wss = reinterpret_cast<const float4*>(s_wss);
    const float4* wde = reinterpret_cast<const float4*>(s_wde);
    const float4* wse = reinterpret_cast<const float4*>(s_wse);

    float ds = 0.f, sv = 0.f, de = 0.f, se = 0.f;
    #pragma unroll
    for (int k = 0; k < HH / 128; k++) {
        int idx = k * 32 + lane;
        float4 r = __ldcs(&r4[idx]);         // streaming: rep is read-once
        float4 a = wds[idx];
        float4 b = wss[idx];
        float4 c = wde[idx];
        float4 d = wse[idx];
        ds += r.x*a.x + r.y*a.y + r.z*a.z + r.w*a.w;
        sv += r.x*b.x + r.y*b.y + r.z*b.z + r.w*b.w;
        de += r.x*c.x + r.y*c.y + r.z*c.z + r.w*c.w;
        se += r.x*d.x + r.y*d.y + r.z*d.z + r.w*d.w;
    }
    #pragma unroll
    for (int off = 16; off; off >>= 1) {
        ds += __shfl_xor_sync(0xffffffffu, ds, off);
        sv += __shfl_xor_sync(0xffffffffu, sv, off);
        de += __shfl_xor_sync(0xffffffffu, de, off);
        se += __shfl_xor_sync(0xffffffffu, se, off);
    }
    if (lane == 0) {
        int m  = (mask[t] != 0);
        int sc = m && ((ds + s_bias[0]) >= 0.f);   // s0 <= s1
        int ec = m && ((de + s_bias[2]) >= 0.f);   // e0 <= e1
        g_sse[t] = sc ? (sv + s_bias[1]) : NEGBIG;
        g_see[t] = ec ? (se + s_bias[3]) : NEGBIG;
    }
}

// ---------------------------------------------------------------------------
// Kernel 2: FOUR rows per block (grid 512 x 8, 512 threads). The se4 row
// vector is loaded ONCE per thread and reused for all 4 rows (pair input
// LDG traffic /4 vs 1-row); per-row scalar ss. Stores __stcs (measured best).
// Same minimal body that won at RPB=2 (R15: pair 39.2us, regs 25).
// ---------------------------------------------------------------------------
__global__ void __launch_bounds__(512)
pair_kernel(float* __restrict__ out_valid,
            float* __restrict__ out_masked)
{
    const int i0 = blockIdx.x * RPB;
    const int b  = blockIdx.y;
    const int j4 = threadIdx.x;        // one float4 (4 j's) per thread
    const int j0 = j4 * 4;

    const float4 se4 = reinterpret_cast<const float4*>(g_see + b * SS)[j4];

    const size_t row0 = ((size_t)b * SS + i0) * SS;
    float4* ov = reinterpret_cast<float4*>(out_valid  + row0) + j4;
    float4* om = reinterpret_cast<float4*>(out_masked + row0) + j4;

    #pragma unroll
    for (int r = 0; r < RPB; r++) {
        const int   i  = i0 + r;
        const float ss = g_sse[b * SS + i];

        float4 v, m;
        if (ss < -1e29f || (j0 + 3) < i) {   // row dead or fully below diagonal
            v = make_float4(0.f, 0.f, 0.f, 0.f);
            m = v;
        } else {
            float ps; bool val;
            ps = ss + se4.x; val = (i <= j0 + 0) && (ps > 0.f);
            v.x = val ? 1.f : 0.f; m.x = val ? ps : 0.f;
            ps = ss + se4.y; val = (i <= j0 + 1) && (ps > 0.f);
            v.y = val ? 1.f : 0.f; m.y = val ? ps : 0.f;
            ps = ss + se4.z; val = (i <= j0 + 2) && (ps > 0.f);
            v.z = val ? 1.f : 0.f; m.z = val ? ps : 0.f;
            ps = ss + se4.w; val = (i <= j0 + 3) && (ps > 0.f);
            v.w = val ? 1.f : 0.f; m.w = val ? ps : 0.f;
        }
        __stcs(ov + (size_t)r * (SS / 4), v);
        __stcs(om + (size_t)r * (SS / 4), m);
    }
}

extern "C" void kernel_launch(void* const* d_in, const int* in_sizes, int n_in,
                              void* d_out, int out_size)
{
    const float* rep  = (const float*)d_in[0];
    const int*   mask = (const int*)  d_in[1];
    const float* Ws   = (const float*)d_in[2];
    const float* bs   = (const float*)d_in[3];
    const float* We   = (const float*)d_in[4];
    const float* be   = (const float*)d_in[5];
    const float* Wm   = (const float*)d_in[6];
    const float* bm   = (const float*)d_in[7];

    float* out = (float*)d_out;
    const size_t half = (size_t)BB * SS * SS;   // valid first, masked second

    logits_kernel<<<NT / 16, 512>>>(rep, mask, Ws, bs, We, be, Wm, bm);

    dim3 g2(SS / RPB, BB);
    pair_kernel<<<g2, 512>>>(out, out + half);
}